// round 5
// baseline (speedup 1.0000x reference)
#include <cuda_runtime.h>
#include <cstdint>

#define OUT_SEGS 100000
#define FDIM 128

// Scratch (allocation-free rule): pooled sums [OUT_SEGS, 128] + counts [OUT_SEGS]
__device__ float g_pooled[(size_t)OUT_SEGS * FDIM];
__device__ float g_count[OUT_SEGS];

// ---------------------------------------------------------------------------
// 1) zero scratch; write pooled with evict-last policy so it is L2-resident
//    and sticky before the scatter's atomics hit it.
__global__ void zero_kernel() {
    uint64_t policy;
    asm volatile("createpolicy.fractional.L2::evict_last.b64 %0, 1.0;"
                 : "=l"(policy));

    size_t total4 = (size_t)OUT_SEGS * FDIM / 4;   // float4 count
    size_t stride = (size_t)gridDim.x * blockDim.x;
    float4* p = reinterpret_cast<float4*>(g_pooled);
    for (size_t i = (size_t)blockIdx.x * blockDim.x + threadIdx.x; i < total4; i += stride) {
        asm volatile("st.global.L2::cache_hint.v4.f32 [%0], {%1, %1, %1, %1}, %2;"
                     :: "l"(p + i), "f"(0.0f), "l"(policy) : "memory");
    }
    for (size_t i = (size_t)blockIdx.x * blockDim.x + threadIdx.x; i < OUT_SEGS; i += stride) {
        asm volatile("st.global.L2::cache_hint.f32 [%0], %1, %2;"
                     :: "l"(g_count + i), "f"(0.0f), "l"(policy) : "memory");
    }
}

// ---------------------------------------------------------------------------
// 2) scatter: half-warp per input row (16 lanes x 32B = 512B row).
//    256-bit streaming load of x (.cs, evict-first) + 2x red.global.add.v4.f32
//    into the L2-resident pooled buffer. 2 rows per warp.
__global__ void scatter_kernel(const float* __restrict__ x,
                               const int* __restrict__ index, int N) {
    int warp_global = (blockIdx.x * blockDim.x + threadIdx.x) >> 5;
    int lane = threadIdx.x & 31;
    int half = lane >> 4;      // 0 or 1
    int h = lane & 15;         // 32B chunk within row

    int row = warp_global * 2 + half;
    if (row >= N) return;

    int seg = index[row];
    const float* src = x + (size_t)row * FDIM + h * 8;

    unsigned r0, r1, r2, r3, r4, r5, r6, r7;
    asm volatile("ld.global.cs.v8.b32 {%0, %1, %2, %3, %4, %5, %6, %7}, [%8];"
                 : "=r"(r0), "=r"(r1), "=r"(r2), "=r"(r3),
                   "=r"(r4), "=r"(r5), "=r"(r6), "=r"(r7)
                 : "l"(src));

    float* dst = g_pooled + (size_t)seg * FDIM + h * 8;
    asm volatile("red.global.add.v4.f32 [%0], {%1, %2, %3, %4};"
                 :: "l"(dst),
                    "f"(__uint_as_float(r0)), "f"(__uint_as_float(r1)),
                    "f"(__uint_as_float(r2)), "f"(__uint_as_float(r3))
                 : "memory");
    asm volatile("red.global.add.v4.f32 [%0], {%1, %2, %3, %4};"
                 :: "l"(dst + 4),
                    "f"(__uint_as_float(r4)), "f"(__uint_as_float(r5)),
                    "f"(__uint_as_float(r6)), "f"(__uint_as_float(r7))
                 : "memory");
    if (h == 0)
        atomicAdd(g_count + seg, 1.0f);
}

// ---------------------------------------------------------------------------
// 3) gather (fused finalize): half-warp per row, 256-bit evict-last loads of
//    pooled (L2-resident), scale by 1/(count+eps), streaming .cs stores.
//    4 rows per warp (2x unroll) for MLP.
__global__ void gather_kernel(const int* __restrict__ index,
                              float* __restrict__ out, int N) {
    int warp_global = (blockIdx.x * blockDim.x + threadIdx.x) >> 5;
    int lane = threadIdx.x & 31;
    int half = lane >> 4;
    int h = lane & 15;

    int base = warp_global * 4;
    int row0 = base + half;
    int row1 = base + 2 + half;
    if (row0 >= N) return;
    bool do1 = (row1 < N);

    int seg0 = index[row0];
    int seg1 = do1 ? index[row1] : seg0;

    const float* p0 = g_pooled + (size_t)seg0 * FDIM + h * 8;
    const float* p1 = g_pooled + (size_t)seg1 * FDIM + h * 8;

    unsigned a0,a1,a2,a3,a4,a5,a6,a7;
    unsigned b0,b1,b2,b3,b4,b5,b6,b7;
    asm volatile("ld.global.nc.L2::evict_last.v8.b32 {%0, %1, %2, %3, %4, %5, %6, %7}, [%8];"
                 : "=r"(a0), "=r"(a1), "=r"(a2), "=r"(a3),
                   "=r"(a4), "=r"(a5), "=r"(a6), "=r"(a7)
                 : "l"(p0));
    asm volatile("ld.global.nc.L2::evict_last.v8.b32 {%0, %1, %2, %3, %4, %5, %6, %7}, [%8];"
                 : "=r"(b0), "=r"(b1), "=r"(b2), "=r"(b3),
                   "=r"(b4), "=r"(b5), "=r"(b6), "=r"(b7)
                 : "l"(p1));

    float c0 = __ldg(g_count + seg0);
    float c1 = __ldg(g_count + seg1);
    float inv0 = 1.0f / (c0 + 1e-9f);
    float inv1 = 1.0f / (c1 + 1e-9f);

    float f0 = __uint_as_float(a0) * inv0, f1 = __uint_as_float(a1) * inv0;
    float f2 = __uint_as_float(a2) * inv0, f3 = __uint_as_float(a3) * inv0;
    float f4 = __uint_as_float(a4) * inv0, f5 = __uint_as_float(a5) * inv0;
    float f6 = __uint_as_float(a6) * inv0, f7 = __uint_as_float(a7) * inv0;

    float* o0 = out + (size_t)row0 * FDIM + h * 8;
    asm volatile("st.global.cs.v4.f32 [%0], {%1, %2, %3, %4};"
                 :: "l"(o0), "f"(f0), "f"(f1), "f"(f2), "f"(f3) : "memory");
    asm volatile("st.global.cs.v4.f32 [%0], {%1, %2, %3, %4};"
                 :: "l"(o0 + 4), "f"(f4), "f"(f5), "f"(f6), "f"(f7) : "memory");

    if (do1) {
        float g0 = __uint_as_float(b0) * inv1, g1 = __uint_as_float(b1) * inv1;
        float g2 = __uint_as_float(b2) * inv1, g3 = __uint_as_float(b3) * inv1;
        float g4 = __uint_as_float(b4) * inv1, g5 = __uint_as_float(b5) * inv1;
        float g6 = __uint_as_float(b6) * inv1, g7 = __uint_as_float(b7) * inv1;

        float* o1 = out + (size_t)row1 * FDIM + h * 8;
        asm volatile("st.global.cs.v4.f32 [%0], {%1, %2, %3, %4};"
                     :: "l"(o1), "f"(g0), "f"(g1), "f"(g2), "f"(g3) : "memory");
        asm volatile("st.global.cs.v4.f32 [%0], {%1, %2, %3, %4};"
                     :: "l"(o1 + 4), "f"(g4), "f"(g5), "f"(g6), "f"(g7) : "memory");
    }
}

// ---------------------------------------------------------------------------
extern "C" void kernel_launch(void* const* d_in, const int* in_sizes, int n_in,
                              void* d_out, int out_size) {
    const float* x   = (const float*)d_in[0];
    const int* index = (const int*)d_in[1];
    float* out = (float*)d_out;

    int N = in_sizes[1];  // number of rows (index has N elements)

    // 1) zero + L2-warm scratch
    zero_kernel<<<1184, 256>>>();

    // 2) scatter: 2 rows per warp
    {
        int threads = 256;
        int rows_per_block = (threads / 32) * 2;
        int blocks = (N + rows_per_block - 1) / rows_per_block;
        scatter_kernel<<<blocks, threads>>>(x, index, N);
    }

    // 3) gather (fused finalize): 4 rows per warp
    {
        int threads = 256;
        int rows_per_block = (threads / 32) * 4;
        int blocks = (N + rows_per_block - 1) / rows_per_block;
        gather_kernel<<<blocks, threads>>>(index, out, N);
    }
}

// round 6
// speedup vs baseline: 1.2960x; 1.2960x over previous
#include <cuda_runtime.h>
#include <cstdint>

#define OUT_SEGS 100000
#define FDIM 128

// Scratch (allocation-free rule): pooled sums [OUT_SEGS, 128] + counts [OUT_SEGS]
__device__ float g_pooled[(size_t)OUT_SEGS * FDIM];
__device__ float g_count[OUT_SEGS];

// ---------------------------------------------------------------------------
// 1) zero scratch (plain stores; 51.2MB fits in L2 and stays warm for scatter)
__global__ void zero_kernel() {
    size_t total = (size_t)OUT_SEGS * FDIM;
    size_t stride = (size_t)gridDim.x * blockDim.x;
    for (size_t i = (size_t)blockIdx.x * blockDim.x + threadIdx.x; i < total; i += stride)
        g_pooled[i] = 0.0f;
    for (size_t i = (size_t)blockIdx.x * blockDim.x + threadIdx.x; i < OUT_SEGS; i += stride)
        g_count[i] = 0.0f;
}

// ---------------------------------------------------------------------------
// 2) scatter: one full warp per input row. Each lane: one 16B chunk via a
//    single red.global.add.v4.f32 -> each REDG instruction covers a dense
//    512B span of one segment row (best L2 atomic wavefront shape).
//    x is streamed once -> ld.global.cs keeps it out of L2.
__global__ void scatter_kernel(const float* __restrict__ x,
                               const int* __restrict__ index, int N) {
    int warp_global = (blockIdx.x * blockDim.x + threadIdx.x) >> 5;
    int lane = threadIdx.x & 31;

    if (warp_global >= N) return;
    int row = warp_global;

    int seg = index[row];
    const float* src = x + (size_t)row * FDIM + lane * 4;
    float4 v;
    asm volatile("ld.global.cs.v4.f32 {%0, %1, %2, %3}, [%4];"
                 : "=f"(v.x), "=f"(v.y), "=f"(v.z), "=f"(v.w)
                 : "l"(src));
    float* dst = g_pooled + (size_t)seg * FDIM + lane * 4;
    asm volatile("red.global.add.v4.f32 [%0], {%1, %2, %3, %4};"
                 :: "l"(dst), "f"(v.x), "f"(v.y), "f"(v.z), "f"(v.w)
                 : "memory");
    if (lane == 0)
        atomicAdd(g_count + seg, 1.0f);
}

// ---------------------------------------------------------------------------
// 3) gather (fused finalize): one warp per 4 output rows, float4 per lane.
//    4 independent pooled loads in flight per warp (hide L2 ~234cyc latency).
//    pooled reads: ld.global.nc.L2::cache_hint (evict-last policy)
//    out writes:   st.global.cs (evict-first)
__global__ void gather_kernel(const int* __restrict__ index,
                              float* __restrict__ out, int N) {
    int warp_global = (blockIdx.x * blockDim.x + threadIdx.x) >> 5;
    int lane = threadIdx.x & 31;

    int row0 = warp_global * 4;
    if (row0 >= N) return;
    int row1 = row0 + 1, row2 = row0 + 2, row3 = row0 + 3;
    bool d1 = row1 < N, d2 = row2 < N, d3 = row3 < N;

    uint64_t policy;
    asm volatile("createpolicy.fractional.L2::evict_last.b64 %0, 1.0;"
                 : "=l"(policy));

    int seg0 = index[row0];
    int seg1 = d1 ? index[row1] : seg0;
    int seg2 = d2 ? index[row2] : seg0;
    int seg3 = d3 ? index[row3] : seg0;

    const float* p0 = g_pooled + (size_t)seg0 * FDIM + lane * 4;
    const float* p1 = g_pooled + (size_t)seg1 * FDIM + lane * 4;
    const float* p2 = g_pooled + (size_t)seg2 * FDIM + lane * 4;
    const float* p3 = g_pooled + (size_t)seg3 * FDIM + lane * 4;

    float4 a, b, c, d;
    asm volatile("ld.global.nc.L2::cache_hint.v4.f32 {%0, %1, %2, %3}, [%4], %5;"
                 : "=f"(a.x), "=f"(a.y), "=f"(a.z), "=f"(a.w)
                 : "l"(p0), "l"(policy));
    asm volatile("ld.global.nc.L2::cache_hint.v4.f32 {%0, %1, %2, %3}, [%4], %5;"
                 : "=f"(b.x), "=f"(b.y), "=f"(b.z), "=f"(b.w)
                 : "l"(p1), "l"(policy));
    asm volatile("ld.global.nc.L2::cache_hint.v4.f32 {%0, %1, %2, %3}, [%4], %5;"
                 : "=f"(c.x), "=f"(c.y), "=f"(c.z), "=f"(c.w)
                 : "l"(p2), "l"(policy));
    asm volatile("ld.global.nc.L2::cache_hint.v4.f32 {%0, %1, %2, %3}, [%4], %5;"
                 : "=f"(d.x), "=f"(d.y), "=f"(d.z), "=f"(d.w)
                 : "l"(p3), "l"(policy));

    float inv0 = 1.0f / (__ldg(g_count + seg0) + 1e-9f);
    float inv1 = 1.0f / (__ldg(g_count + seg1) + 1e-9f);
    float inv2 = 1.0f / (__ldg(g_count + seg2) + 1e-9f);
    float inv3 = 1.0f / (__ldg(g_count + seg3) + 1e-9f);

    a.x *= inv0; a.y *= inv0; a.z *= inv0; a.w *= inv0;
    b.x *= inv1; b.y *= inv1; b.z *= inv1; b.w *= inv1;
    c.x *= inv2; c.y *= inv2; c.z *= inv2; c.w *= inv2;
    d.x *= inv3; d.y *= inv3; d.z *= inv3; d.w *= inv3;

    float* o0 = out + (size_t)row0 * FDIM + lane * 4;
    asm volatile("st.global.cs.v4.f32 [%0], {%1, %2, %3, %4};"
                 :: "l"(o0), "f"(a.x), "f"(a.y), "f"(a.z), "f"(a.w) : "memory");
    if (d1) {
        float* o1 = out + (size_t)row1 * FDIM + lane * 4;
        asm volatile("st.global.cs.v4.f32 [%0], {%1, %2, %3, %4};"
                     :: "l"(o1), "f"(b.x), "f"(b.y), "f"(b.z), "f"(b.w) : "memory");
    }
    if (d2) {
        float* o2 = out + (size_t)row2 * FDIM + lane * 4;
        asm volatile("st.global.cs.v4.f32 [%0], {%1, %2, %3, %4};"
                     :: "l"(o2), "f"(c.x), "f"(c.y), "f"(c.z), "f"(c.w) : "memory");
    }
    if (d3) {
        float* o3 = out + (size_t)row3 * FDIM + lane * 4;
        asm volatile("st.global.cs.v4.f32 [%0], {%1, %2, %3, %4};"
                     :: "l"(o3), "f"(d.x), "f"(d.y), "f"(d.z), "f"(d.w) : "memory");
    }
}

// ---------------------------------------------------------------------------
extern "C" void kernel_launch(void* const* d_in, const int* in_sizes, int n_in,
                              void* d_out, int out_size) {
    const float* x   = (const float*)d_in[0];
    const int* index = (const int*)d_in[1];
    float* out = (float*)d_out;

    int N = in_sizes[1];  // number of rows (index has N elements)

    // 1) zero scratch
    zero_kernel<<<1184, 256>>>();

    // 2) scatter: warp per row
    {
        int threads = 256;
        int warps_per_block = threads / 32;
        int blocks = (N + warps_per_block - 1) / warps_per_block;
        scatter_kernel<<<blocks, threads>>>(x, index, N);
    }

    // 3) gather (fused finalize): warp per 4 rows
    {
        int threads = 256;
        int rows_per_block = (threads / 32) * 4;
        int blocks = (N + rows_per_block - 1) / rows_per_block;
        gather_kernel<<<blocks, threads>>>(index, out, N);
    }
}